// round 10
// baseline (speedup 1.0000x reference)
#include <cuda_runtime.h>
#include <cuda_fp16.h>
#include <stdint.h>
#include <math.h>

// ---------------- problem constants ----------------------------------------
#define BB   8
#define CC   512
#define SS   256
#define TT   8192
#define DIL  4
#define NTOT (BB*TT)       // 65536
#define K1   (2*CC)        // 1024 reduction dim GEMM1
#define M1   (2*CC)        // 1024 rows of W1 (F/G interleaved)
#define M2   (CC+SS)       // 768 rows GEMM2
#define KC   64            // k halfs per smem stage (4 mma k-steps of 16)
#define HST  72            // smem row stride in halfs (144B): conflict-free
#define NST  3             // pipeline stages
#define SZT  72            // epilogue staging stride (halfs, 16B-aligned rows)
#define SQRT_HALF 0.70710678118654752440f

// ---------------- device scratch --------------------------------------------
__device__ __align__(16) __half g_xT[(size_t)NTOT*CC];  // [b][t][c]
__device__ __align__(16) __half g_zT[(size_t)NTOT*CC];  // [b][t][c]
__device__ __align__(16) __half g_W1[M1*K1];            // [o=2c+g][k]
__device__ __align__(16) __half g_W2[M2*CC];            // [m][k]
__device__ __align__(16) __half g_zero[16];             // zero-init (causal pad)

// ---------------- helpers ----------------------------------------------------
__device__ __forceinline__ void mma16(float* c, const uint32_t* a, const uint32_t* b) {
    asm volatile(
        "mma.sync.aligned.m16n8k16.row.col.f32.f16.f16.f32 "
        "{%0,%1,%2,%3}, {%4,%5,%6,%7}, {%8,%9}, {%0,%1,%2,%3};"
        : "+f"(c[0]), "+f"(c[1]), "+f"(c[2]), "+f"(c[3])
        : "r"(a[0]), "r"(a[1]), "r"(a[2]), "r"(a[3]), "r"(b[0]), "r"(b[1]));
}
__device__ __forceinline__ void ldsm4(uint32_t& r0, uint32_t& r1, uint32_t& r2,
                                      uint32_t& r3, uint32_t addr) {
    asm volatile("ldmatrix.sync.aligned.m8n8.x4.shared.b16 {%0,%1,%2,%3}, [%4];"
                 : "=r"(r0), "=r"(r1), "=r"(r2), "=r"(r3) : "r"(addr));
}
__device__ __forceinline__ void cpa16(uint32_t dst, const void* src) {
    asm volatile("cp.async.cg.shared.global [%0], [%1], 16;" :: "r"(dst), "l"(src));
}
#define CP_COMMIT() asm volatile("cp.async.commit_group;" ::: "memory")
#define CP_WAIT1()  asm volatile("cp.async.wait_group 1;" ::: "memory")

#define STAGE (128*HST)                     // halfs per operand stage
#define SMEM_DYN (2*NST*STAGE*2)            // bytes: A[NST] + B[NST]

// ---------------- transpose + pack ------------------------------------------
__global__ void transpose_x(const float* __restrict__ x) {
    __shared__ float tile[32][33];
    const int b = blockIdx.z, c0 = blockIdx.y * 32, t0 = blockIdx.x * 32;
    const int tx = threadIdx.x, ty = threadIdx.y;
    const float* xb = x + ((size_t)b * CC + c0) * TT + t0;
    #pragma unroll
    for (int i = 0; i < 4; i++) tile[ty + 8 * i][tx] = xb[(ty + 8 * i) * TT + tx];
    __syncthreads();
    __half* xt = g_xT + ((size_t)b * TT + t0) * CC + c0;
    #pragma unroll
    for (int i = 0; i < 4; i++)
        xt[(size_t)(ty + 8 * i) * CC + tx] = __float2half_rn(tile[tx][ty + 8 * i]);
}
__global__ void pack_w1(const float* __restrict__ fw, const float* __restrict__ gw) {
    int idx = blockIdx.x * blockDim.x + threadIdx.x;
    if (idx >= M1 * K1) return;
    int o = idx / K1, k = idx % K1;
    int co = o >> 1, ci = k & (CC - 1);
    int tap = (k < CC) ? 1 : 0;     // k<512: x[t], k>=512: x[t-4]
    const float* w = (o & 1) ? gw : fw;
    g_W1[idx] = __float2half_rn(w[(co * CC + ci) * 2 + tap]);
}
__global__ void pack_w2(const float* __restrict__ rw, const float* __restrict__ sw) {
    int idx = blockIdx.x * blockDim.x + threadIdx.x;
    if (idx >= M2 * CC) return;
    int m = idx / CC, k = idx % CC;
    g_W2[idx] = __float2half_rn((m < CC) ? rw[m * CC + k] : sw[(m - CC) * CC + k]);
}

// ---------------- GEMM1: D[t][2c+g] = xT2 @ W1^T, fused gating --------------
// CTA 128(t) x 128(interleaved outch); 8 warps 2x4; warp tile 64x32. fp16 MMA.
__global__ void __launch_bounds__(256, 2)
gemm1(const float* __restrict__ fbias, const float* __restrict__ gbias)
{
    extern __shared__ __half hsm[];
    __half* sA = hsm;                  // [NST][128*HST]
    __half* sB = hsm + NST * STAGE;

    const int tid = threadIdx.x, lane = tid & 31, wid = tid >> 5;
    const int wm = wid >> 2, wn = wid & 3;
    const int nb = blockIdx.x;                    // 8 outch-tiles
    const int tb = blockIdx.y;                    // 512 t-tiles
    const int base = tb * 128;
    const int b = base / TT;
    const int t0 = base % TT;
    const int n0 = nb * 128;
    const __half* __restrict__ xTb = g_xT + (size_t)b * TT * CC;

    const uint32_t sA_u = (uint32_t)__cvta_generic_to_shared(sA);
    const uint32_t sB_u = (uint32_t)__cvta_generic_to_shared(sB);

    float acc[4][4][4];
    #pragma unroll
    for (int i = 0; i < 4; i++)
        #pragma unroll
        for (int j = 0; j < 4; j++)
            #pragma unroll
            for (int q = 0; q < 4; q++) acc[i][j][q] = 0.f;

    const int arow = tid >> 3, ac8 = (tid & 7) * 8;
    auto issue = [&](int st, int k0) {
        const int sh = (k0 >= CC) ? DIL : 0;
        const int kk = k0 & (CC - 1);
        #pragma unroll
        for (int i = 0; i < 4; i++) {
            int row = arow + i * 32;
            int t = t0 + row - sh;
            const __half* srcA = (t >= 0) ? &xTb[(size_t)t * CC + kk + ac8]
                                          : &g_zero[0];
            cpa16(sA_u + (st * STAGE + row * HST + ac8) * 2, srcA);
            cpa16(sB_u + (st * STAGE + row * HST + ac8) * 2,
                  &g_W1[(size_t)(n0 + row) * K1 + k0 + ac8]);
        }
    };

    issue(0, 0);  CP_COMMIT();
    issue(1, KC); CP_COMMIT();

    // ldmatrix fragment base addresses (x4 geometry: lanes 0-15 rows, 16-31 +8 cols)
    const uint32_t aFrag = sA_u + ((wm * 64 + (lane & 15)) * HST + (lane >> 4) * 8) * 2;
    const uint32_t bFrag = sB_u + ((wn * 32 + (lane & 15)) * HST + (lane >> 4) * 8) * 2;

    const int NC = K1 / KC;   // 16
    int st = 0;
    for (int c = 0; c < NC; c++) {
        CP_WAIT1();
        __syncthreads();
        if (c + 2 < NC) issue((c + 2) % NST, (c + 2) * KC);
        CP_COMMIT();
        const uint32_t aS = aFrag + st * (STAGE * 2);
        const uint32_t bS = bFrag + st * (STAGE * 2);
        #pragma unroll
        for (int ks = 0; ks < 4; ks++) {
            uint32_t af[4][4], bf[4][2];
            #pragma unroll
            for (int mi = 0; mi < 4; mi++)
                ldsm4(af[mi][0], af[mi][1], af[mi][2], af[mi][3],
                      aS + mi * (16 * HST * 2) + ks * 32);
            #pragma unroll
            for (int np = 0; np < 2; np++) {
                uint32_t r0, r1, r2, r3;
                ldsm4(r0, r1, r2, r3, bS + np * (16 * HST * 2) + ks * 32);
                bf[2*np][0] = r0; bf[2*np+1][0] = r1;
                bf[2*np][1] = r2; bf[2*np+1][1] = r3;
            }
            #pragma unroll
            for (int mi = 0; mi < 4; mi++)
                #pragma unroll
                for (int ni = 0; ni < 4; ni++)
                    mma16(acc[mi][ni], af[mi], bf[ni]);
        }
        st = (st + 1) % NST;
    }
    __syncthreads();   // all MMA smem reads done; safe to reuse for staging

    // ---- epilogue: gate, stage in smem, coalesced 16B row writes ------------
    __half* sz = hsm;                             // [128][SZT]
    #pragma unroll
    for (int mi = 0; mi < 4; mi++) {
        const int tl = wm * 64 + mi * 16 + (lane >> 2);
        #pragma unroll
        for (int ni = 0; ni < 4; ni++) {
            const int chl = wn * 16 + ni * 4 + (lane & 3);
            const int ch = nb * 64 + chl;
            const float fb = fbias[ch], gb = gbias[ch];
            float F0 = acc[mi][ni][0] + fb;
            float G0 = acc[mi][ni][1] + gb;
            float F1 = acc[mi][ni][2] + fb;
            float G1 = acc[mi][ni][3] + gb;
            sz[tl * SZT + chl] =
                __float2half_rn(tanhf(F0) * (1.f / (1.f + __expf(-G0))));
            sz[(tl + 8) * SZT + chl] =
                __float2half_rn(tanhf(F1) * (1.f / (1.f + __expf(-G1))));
        }
    }
    __syncthreads();
    __half* __restrict__ zb = g_zT + (size_t)b * TT * CC;
    const int c8 = tid & 7, trow = tid >> 3;      // 32 rows x 8 col-chunks
    #pragma unroll
    for (int i = 0; i < 4; i++) {
        int t = trow + i * 32;
        *(uint4*)&zb[(size_t)(t0 + t) * CC + nb * 64 + c8 * 8] =
            *(const uint4*)&sz[t * SZT + c8 * 8];
    }
}

// ---------------- GEMM2: D[m][t] = W2 @ zT^T, fused residual/skip -----------
// CTA 128(m) x 128(t); 8 warps 2x4; warp tile 64x32. fp16 MMA.
__global__ void __launch_bounds__(256, 2)
gemm2(const float* __restrict__ x,
      const float* __restrict__ rbias, const float* __restrict__ sbias,
      float* __restrict__ out)
{
    extern __shared__ __half hsm[];
    __half* sA = hsm;
    __half* sB = hsm + NST * STAGE;

    const int tid = threadIdx.x, lane = tid & 31, wid = tid >> 5;
    const int wm = wid >> 2, wn = wid & 3;
    const int mb = blockIdx.x;                    // 6 m-tiles
    const int tb = blockIdx.y;                    // 512 t-tiles
    const int base = tb * 128;
    const int b = base / TT;
    const int t0 = base % TT;
    const int m0 = mb * 128;
    const __half* __restrict__ zTb = g_zT + (size_t)b * TT * CC;

    const uint32_t sA_u = (uint32_t)__cvta_generic_to_shared(sA);
    const uint32_t sB_u = (uint32_t)__cvta_generic_to_shared(sB);

    float acc[4][4][4];
    #pragma unroll
    for (int i = 0; i < 4; i++)
        #pragma unroll
        for (int j = 0; j < 4; j++)
            #pragma unroll
            for (int q = 0; q < 4; q++) acc[i][j][q] = 0.f;

    const int arow = tid >> 3, ac8 = (tid & 7) * 8;
    auto issue = [&](int st, int k0) {
        #pragma unroll
        for (int i = 0; i < 4; i++) {
            int row = arow + i * 32;
            cpa16(sA_u + (st * STAGE + row * HST + ac8) * 2,
                  &g_W2[(size_t)(m0 + row) * CC + k0 + ac8]);
            cpa16(sB_u + (st * STAGE + row * HST + ac8) * 2,
                  &zTb[(size_t)(t0 + row) * CC + k0 + ac8]);
        }
    };

    issue(0, 0);  CP_COMMIT();
    issue(1, KC); CP_COMMIT();

    const uint32_t aFrag = sA_u + ((wm * 64 + (lane & 15)) * HST + (lane >> 4) * 8) * 2;
    const uint32_t bFrag = sB_u + ((wn * 32 + (lane & 15)) * HST + (lane >> 4) * 8) * 2;

    const int NC = CC / KC;   // 8
    int st = 0;
    for (int c = 0; c < NC; c++) {
        CP_WAIT1();
        __syncthreads();
        if (c + 2 < NC) issue((c + 2) % NST, (c + 2) * KC);
        CP_COMMIT();
        const uint32_t aS = aFrag + st * (STAGE * 2);
        const uint32_t bS = bFrag + st * (STAGE * 2);
        #pragma unroll
        for (int ks = 0; ks < 4; ks++) {
            uint32_t af[4][4], bf[4][2];
            #pragma unroll
            for (int mi = 0; mi < 4; mi++)
                ldsm4(af[mi][0], af[mi][1], af[mi][2], af[mi][3],
                      aS + mi * (16 * HST * 2) + ks * 32);
            #pragma unroll
            for (int np = 0; np < 2; np++) {
                uint32_t r0, r1, r2, r3;
                ldsm4(r0, r1, r2, r3, bS + np * (16 * HST * 2) + ks * 32);
                bf[2*np][0] = r0; bf[2*np+1][0] = r1;
                bf[2*np][1] = r2; bf[2*np+1][1] = r3;
            }
            #pragma unroll
            for (int mi = 0; mi < 4; mi++)
                #pragma unroll
                for (int ni = 0; ni < 4; ni++)
                    mma16(acc[mi][ni], af[mi], bf[ni]);
        }
        st = (st + 1) % NST;
    }

    // ---- epilogue: rows m (channels), cols t ---------------------------------
    #pragma unroll
    for (int mi = 0; mi < 4; mi++) {
        #pragma unroll
        for (int half = 0; half < 2; half++) {
            const int m = m0 + wm * 64 + mi * 16 + (lane >> 2) + half * 8;
            if (m < CC) {
                const float rbv = rbias[m];
                const float* __restrict__ xrow = x + ((size_t)b * CC + m) * TT;
                float* __restrict__ orow = out + ((size_t)b * CC + m) * TT;
                #pragma unroll
                for (int ni = 0; ni < 4; ni++) {
                    const int t = t0 + wn * 32 + ni * 8 + (lane & 3) * 2;
                    float2 xv = *(const float2*)&xrow[t];
                    float2 o;
                    o.x = (xv.x + acc[mi][ni][half * 2]     + rbv) * SQRT_HALF;
                    o.y = (xv.y + acc[mi][ni][half * 2 + 1] + rbv) * SQRT_HALF;
                    *(float2*)&orow[t] = o;
                }
            } else {
                const int s = m - CC;
                const float sbv = sbias[s];
                float* __restrict__ orow =
                    out + (size_t)BB * CC * TT + ((size_t)b * SS + s) * TT;
                #pragma unroll
                for (int ni = 0; ni < 4; ni++) {
                    const int t = t0 + wn * 32 + ni * 8 + (lane & 3) * 2;
                    float2 o;
                    o.x = acc[mi][ni][half * 2]     + sbv;
                    o.y = acc[mi][ni][half * 2 + 1] + sbv;
                    *(float2*)&orow[t] = o;
                }
            }
        }
    }
}

// ---------------- launch -----------------------------------------------------
extern "C" void kernel_launch(void* const* d_in, const int* in_sizes, int n_in,
                              void* d_out, int out_size)
{
    const float* x  = (const float*)d_in[0];
    const float* fw = (const float*)d_in[1];
    const float* fb = (const float*)d_in[2];
    const float* gw = (const float*)d_in[3];
    const float* gb = (const float*)d_in[4];
    const float* rw = (const float*)d_in[5];
    const float* rb = (const float*)d_in[6];
    const float* sw = (const float*)d_in[7];
    const float* sb = (const float*)d_in[8];
    float* out = (float*)d_out;

    cudaFuncSetAttribute(gemm1, cudaFuncAttributeMaxDynamicSharedMemorySize, SMEM_DYN);
    cudaFuncSetAttribute(gemm2, cudaFuncAttributeMaxDynamicSharedMemorySize, SMEM_DYN);

    transpose_x<<<dim3(TT / 32, CC / 32, BB), dim3(32, 8)>>>(x);
    pack_w1<<<(M1 * K1 + 255) / 256, 256>>>(fw, gw);
    pack_w2<<<(M2 * CC + 255) / 256, 256>>>(rw, sw);
    gemm1<<<dim3(M1 / 128, NTOT / 128), 256, SMEM_DYN>>>(fb, gb);
    gemm2<<<dim3(M2 / 128, NTOT / 128), 256, SMEM_DYN>>>(x, rb, sb, out);
}